// round 1
// baseline (speedup 1.0000x reference)
#include <cuda_runtime.h>
#include <cuda_bf16.h>
#include <math.h>

// Problem constants
#define BATCH 4
#define SEQ   2048
#define SP    2064            // padded sequence (pad = 16)
#define DIM   1024
#define NH    16
#define QL    16              // q/k head size
#define VL    64              // v head size
#define NTOT  3072            // 1536 value cols + 1536 gate cols
#define NHALF 1536
#define MROWS (BATCH*SEQ)     // 8192

// -------- device scratch (static allocation; no cudaMalloc allowed) --------
__device__ float g_Wall[DIM * NTOT];          // packed [1024,3072] weights
__device__ float g_ball[NTOT];                // packed biases
__device__ float g_lin[(size_t)MROWS * NTOT]; // raw GEMM out [8192,3072]
__device__ float g_q[(size_t)BATCH * NH * SP * QL];
__device__ float g_k[(size_t)BATCH * NH * SP * QL];
__device__ float g_v[(size_t)BATCH * NH * SP * VL];

// ---------------------------------------------------------------------------
// Pack weights: column order [Wq(256)|Wk(256)|Wv(1024) | Wqc|Wkc|Wvc]
// ---------------------------------------------------------------------------
__global__ void pack_weights(const float* __restrict__ Wq,  const float* __restrict__ bq,
                             const float* __restrict__ Wqc, const float* __restrict__ bqc,
                             const float* __restrict__ Wk,  const float* __restrict__ bk,
                             const float* __restrict__ Wkc, const float* __restrict__ bkc,
                             const float* __restrict__ Wv,  const float* __restrict__ bv,
                             const float* __restrict__ Wvc, const float* __restrict__ bvc) {
    int idx = blockIdx.x * blockDim.x + threadIdx.x;
    if (idx < DIM * NTOT) {
        int r = idx / NTOT, j = idx % NTOT;
        int jj = j % NHALF;
        bool gate = (j >= NHALF);
        float w;
        if (jj < 256)      w = gate ? Wqc[r*256 + jj]        : Wq[r*256 + jj];
        else if (jj < 512) w = gate ? Wkc[r*256 + (jj-256)]  : Wk[r*256 + (jj-256)];
        else               w = gate ? Wvc[r*1024 + (jj-512)] : Wv[r*1024 + (jj-512)];
        g_Wall[idx] = w;
    }
    if (idx < NTOT) {
        int j = idx;
        int jj = j % NHALF;
        bool gate = (j >= NHALF);
        float bb;
        if (jj < 256)      bb = gate ? bqc[jj]      : bq[jj];
        else if (jj < 512) bb = gate ? bkc[jj-256]  : bk[jj-256];
        else               bb = gate ? bvc[jj-512]  : bv[jj-512];
        g_ball[j] = bb;
    }
}

// ---------------------------------------------------------------------------
// SGEMM: C[8192,3072] = A[8192,1024] @ g_Wall[1024,3072]
// 128x128 tile, BK=8, 256 threads, 8x8 register micro-tile
// ---------------------------------------------------------------------------
#define BM 128
#define BN 128
#define BK 8

__global__ __launch_bounds__(256) void sgemm_kernel(const float* __restrict__ A) {
    __shared__ float As[BK][BM];   // transposed for broadcast reads
    __shared__ float Bs[BK][BN];

    const int tid = threadIdx.x;
    const int bm = blockIdx.y * BM;
    const int bn = blockIdx.x * BN;

    const int arow = tid >> 1;            // 0..127
    const int acol = (tid & 1) * 4;       // 0 or 4
    const int brow = tid >> 5;            // 0..7
    const int bcol = (tid & 31) * 4;      // 0..124

    const int ty = tid >> 4, tx = tid & 15;

    float acc[8][8];
    #pragma unroll
    for (int i = 0; i < 8; i++)
        #pragma unroll
        for (int j = 0; j < 8; j++) acc[i][j] = 0.f;

    for (int k0 = 0; k0 < DIM; k0 += BK) {
        float4 a4 = *(const float4*)&A[(size_t)(bm + arow) * DIM + k0 + acol];
        As[acol+0][arow] = a4.x;
        As[acol+1][arow] = a4.y;
        As[acol+2][arow] = a4.z;
        As[acol+3][arow] = a4.w;
        float4 b4 = *(const float4*)&g_Wall[(size_t)(k0 + brow) * NTOT + bn + bcol];
        *(float4*)&Bs[brow][bcol] = b4;
        __syncthreads();

        #pragma unroll
        for (int kk = 0; kk < BK; kk++) {
            float ar[8], br[8];
            #pragma unroll
            for (int i = 0; i < 8; i++) ar[i] = As[kk][ty*8 + i];
            #pragma unroll
            for (int j = 0; j < 8; j++) br[j] = Bs[kk][tx*8 + j];
            #pragma unroll
            for (int i = 0; i < 8; i++)
                #pragma unroll
                for (int j = 0; j < 8; j++)
                    acc[i][j] += ar[i] * br[j];
        }
        __syncthreads();
    }

    #pragma unroll
    for (int i = 0; i < 8; i++) {
        float* crow = &g_lin[(size_t)(bm + ty*8 + i) * NTOT + bn + tx*8];
        #pragma unroll
        for (int j = 0; j < 8; j += 4)
            *(float4*)&crow[j] = make_float4(acc[i][j], acc[i][j+1], acc[i][j+2], acc[i][j+3]);
    }
}

// ---------------------------------------------------------------------------
// CSS gating + scatter to q/k/v (per-head, padded-seq layouts).
// Padded rows (s >= SEQ) get the bias-only constant: b * sigmoid(bc).
// ---------------------------------------------------------------------------
__global__ void css_scatter() {
    int idx = blockIdx.x * blockDim.x + threadIdx.x;
    const int total = BATCH * SP * NHALF;
    if (idx >= total) return;
    int j = idx % NHALF;
    int t = idx / NHALF;
    int s = t % SP;
    int b = t / SP;

    float a = 0.f, g = 0.f;
    if (s < SEQ) {
        const float* row = g_lin + (size_t)(b * SEQ + s) * NTOT;
        a = row[j];
        g = row[NHALF + j];
    }
    a += g_ball[j];
    g += g_ball[NHALF + j];
    float val = a * (1.f / (1.f + __expf(-g)));

    if (j < 256) {
        int h = j >> 4, d = j & 15;
        g_q[((size_t)(b*NH + h) * SP + s) * QL + d] = val;
    } else if (j < 512) {
        int jj = j - 256; int h = jj >> 4, d = jj & 15;
        g_k[((size_t)(b*NH + h) * SP + s) * QL + d] = val;
    } else {
        int jj = j - 512; int h = jj >> 6, d = jj & 63;
        g_v[((size_t)(b*NH + h) * SP + s) * VL + d] = val;
    }
}

// ---------------------------------------------------------------------------
// Flash attention. Grid: (32 q-tiles of 64, 16 heads, 4 batch), 256 threads.
// Thread (qr = tid/4, c = tid%4): owns q-row qr, v-cols [c*16, c*16+16),
// computes scores for keys [c*16, c*16+16) each tile; probs exchanged via smem
// within the owning quad (same warp, no cross-warp sync needed for p_s).
// ---------------------------------------------------------------------------
__global__ __launch_bounds__(256) void attn_kernel(float* __restrict__ out) {
    const int qt = blockIdx.x, h = blockIdx.y, b = blockIdx.z;
    const int bh = b * NH + h;
    const float* qbase = g_q + ((size_t)bh * SP + qt * 64) * QL;
    const float* kbase = g_k + (size_t)bh * SP * QL;
    const float* vbase = g_v + (size_t)bh * SP * VL;

    __shared__ float k_s[QL][64];   // d-major k tile
    __shared__ float v_s[64][VL];
    __shared__ float p_s[64][64];

    const int tid = threadIdx.x;
    const int qr = tid >> 2;   // 0..63
    const int c  = tid & 3;    // 0..3

    float qreg[QL];
    {
        const float4* qp = (const float4*)(qbase + qr * QL);
        #pragma unroll
        for (int i = 0; i < 4; i++) {
            float4 t4 = qp[i];
            qreg[i*4+0] = t4.x; qreg[i*4+1] = t4.y;
            qreg[i*4+2] = t4.z; qreg[i*4+3] = t4.w;
        }
    }

    float m_run = -1e30f, l_run = 0.f;
    float O[16];
    #pragma unroll
    for (int j = 0; j < 16; j++) O[j] = 0.f;

    const int NKT = (SP + 63) / 64;   // 33 tiles (last has 16 keys)
    for (int kt = 0; kt < NKT; kt++) {
        const int krow0 = kt * 64;
        // ---- load k tile (transposed) ----
        {
            int key = tid >> 2;
            int dc = (tid & 3) * 4;
            int gk = krow0 + key;
            float4 kv = (gk < SP) ? *(const float4*)(kbase + (size_t)gk * QL + dc)
                                  : make_float4(0.f, 0.f, 0.f, 0.f);
            k_s[dc+0][key] = kv.x; k_s[dc+1][key] = kv.y;
            k_s[dc+2][key] = kv.z; k_s[dc+3][key] = kv.w;
        }
        // ---- load v tile ----
        #pragma unroll
        for (int r = 0; r < 4; r++) {
            int key = r * 16 + (tid >> 4);
            int dc = (tid & 15) * 4;
            int gk = krow0 + key;
            float4 vv = (gk < SP) ? *(const float4*)(vbase + (size_t)gk * VL + dc)
                                  : make_float4(0.f, 0.f, 0.f, 0.f);
            *(float4*)&v_s[key][dc] = vv;
        }
        __syncthreads();

        // ---- scores for my 16 keys ----
        float s[16];
        #pragma unroll
        for (int kk = 0; kk < 16; kk++) s[kk] = 0.f;
        #pragma unroll
        for (int d = 0; d < QL; d++) {
            float qd = qreg[d];
            #pragma unroll
            for (int kk = 0; kk < 16; kk++)
                s[kk] += qd * k_s[d][c*16 + kk];
        }
        const int nk = SP - krow0;   // valid keys this tile
        float m_t = -1e30f;
        #pragma unroll
        for (int kk = 0; kk < 16; kk++) {
            s[kk] = (c*16 + kk < nk) ? s[kk] * 0.125f : -1e30f;
            m_t = fmaxf(m_t, s[kk]);
        }
        m_t = fmaxf(m_t, __shfl_xor_sync(0xffffffffu, m_t, 1, 4));
        m_t = fmaxf(m_t, __shfl_xor_sync(0xffffffffu, m_t, 2, 4));

        float m_new = fmaxf(m_run, m_t);
        float alpha = __expf(m_run - m_new);
        float lsum = 0.f;
        float p[16];
        #pragma unroll
        for (int kk = 0; kk < 16; kk++) {
            p[kk] = __expf(s[kk] - m_new);
            lsum += p[kk];
        }
        lsum += __shfl_xor_sync(0xffffffffu, lsum, 1, 4);
        lsum += __shfl_xor_sync(0xffffffffu, lsum, 2, 4);
        l_run = l_run * alpha + lsum;
        m_run = m_new;
        #pragma unroll
        for (int j = 0; j < 16; j++) O[j] *= alpha;

        // probs to smem (row qr owned by this quad only)
        #pragma unroll
        for (int kk = 0; kk < 16; kk += 4)
            *(float4*)&p_s[qr][c*16 + kk] = make_float4(p[kk], p[kk+1], p[kk+2], p[kk+3]);
        __syncwarp();

        // ---- PV: all 64 keys x my 16 cols ----
        #pragma unroll 8
        for (int key = 0; key < 64; key++) {
            float pp = p_s[qr][key];
            #pragma unroll
            for (int j = 0; j < 16; j++)
                O[j] += pp * v_s[key][c*16 + j];
        }
        __syncthreads();
    }

    float inv = 1.f / l_run;
    float* op = out + ((size_t)(b * SEQ + qt * 64 + qr)) * (NH * VL) + h * VL + c * 16;
    #pragma unroll
    for (int j = 0; j < 16; j += 4)
        *(float4*)&op[j] = make_float4(O[j]*inv, O[j+1]*inv, O[j+2]*inv, O[j+3]*inv);
}

// ---------------------------------------------------------------------------
extern "C" void kernel_launch(void* const* d_in, const int* in_sizes, int n_in,
                              void* d_out, int out_size) {
    const float* x   = (const float*)d_in[0];
    const float* Wq  = (const float*)d_in[1];
    const float* bq  = (const float*)d_in[2];
    const float* Wqc = (const float*)d_in[3];
    const float* bqc = (const float*)d_in[4];
    const float* Wk  = (const float*)d_in[5];
    const float* bk  = (const float*)d_in[6];
    const float* Wkc = (const float*)d_in[7];
    const float* bkc = (const float*)d_in[8];
    const float* Wv  = (const float*)d_in[9];
    const float* bv  = (const float*)d_in[10];
    const float* Wvc = (const float*)d_in[11];
    const float* bvc = (const float*)d_in[12];
    float* out = (float*)d_out;

    pack_weights<<<(DIM*NTOT + 255)/256, 256>>>(Wq,bq,Wqc,bqc,Wk,bk,Wkc,bkc,Wv,bv,Wvc,bvc);

    dim3 gg(NTOT / BN, MROWS / BM);
    sgemm_kernel<<<gg, 256>>>(x);

    css_scatter<<<(BATCH*SP*NHALF + 255)/256, 256>>>();

    dim3 ga(SEQ / 64, NH, BATCH);
    attn_kernel<<<ga, 256>>>(out);
}

// round 2
// speedup vs baseline: 1.8938x; 1.8938x over previous
#include <cuda_runtime.h>
#include <cuda_bf16.h>
#include <math.h>

// Problem constants
#define BATCH 4
#define SEQ   2048
#define SP    2064            // padded sequence (pad = 16)
#define DIM   1024
#define NH    16
#define QL    16              // q/k head size
#define VL    64              // v head size
#define NTOT  3072            // interleaved: col 2p = value, col 2p+1 = gate
#define NPAIR 1536
#define MROWS (BATCH*SEQ)     // 8192

// -------- device scratch --------
__device__ float g_Wall[DIM * NTOT];   // packed interleaved [1024,3072]
__device__ float g_ball[NTOT];
__device__ float g_q[(size_t)BATCH * NH * QL * SP];   // [bh][d][SP]
__device__ float g_k[(size_t)BATCH * NH * QL * SP];   // [bh][d][SP]
__device__ float g_v[(size_t)BATCH * NH * SP * VL];   // [bh][s][d]

// ---------------------------------------------------------------------------
// Pack weights interleaved: packed col j = 2p + gate.
// pair p: p<256 -> q col p; p<512 -> k col p-256; else v col p-512.
// ---------------------------------------------------------------------------
__global__ void pack_weights(const float* __restrict__ Wq,  const float* __restrict__ bq,
                             const float* __restrict__ Wqc, const float* __restrict__ bqc,
                             const float* __restrict__ Wk,  const float* __restrict__ bk,
                             const float* __restrict__ Wkc, const float* __restrict__ bkc,
                             const float* __restrict__ Wv,  const float* __restrict__ bv,
                             const float* __restrict__ Wvc, const float* __restrict__ bvc) {
    int idx = blockIdx.x * blockDim.x + threadIdx.x;
    if (idx < DIM * NTOT) {
        int r = idx / NTOT, j = idx % NTOT;
        int p = j >> 1;
        bool gate = (j & 1);
        float w;
        if (p < 256)      w = gate ? Wqc[r*256 + p]         : Wq[r*256 + p];
        else if (p < 512) w = gate ? Wkc[r*256 + (p-256)]   : Wk[r*256 + (p-256)];
        else              w = gate ? Wvc[r*1024 + (p-512)]  : Wv[r*1024 + (p-512)];
        g_Wall[idx] = w;
    }
    if (idx < NTOT) {
        int p = idx >> 1;
        bool gate = (idx & 1);
        float bb;
        if (p < 256)      bb = gate ? bqc[p]       : bq[p];
        else if (p < 512) bb = gate ? bkc[p-256]   : bk[p-256];
        else              bb = gate ? bvc[p-512]   : bv[p-512];
        g_ball[idx] = bb;
    }
}

// ---------------------------------------------------------------------------
// Scatter one pair of gated values (value-cols P and P+1) for row (b,s)
// ---------------------------------------------------------------------------
__device__ __forceinline__ void scatter2(int P, int b, int s, float v0, float v1) {
    if (P < 256) {
        int h = P >> 4, d = P & 15;
        size_t base = ((size_t)((b*NH + h)*QL + d))*SP + s;
        g_q[base]      = v0;
        g_q[base + SP] = v1;
    } else if (P < 512) {
        int l = P - 256; int h = l >> 4, d = l & 15;
        size_t base = ((size_t)((b*NH + h)*QL + d))*SP + s;
        g_k[base]      = v0;
        g_k[base + SP] = v1;
    } else {
        int l = P - 512; int h = l >> 6, d = l & 63;
        *(float2*)&g_v[((size_t)(b*NH + h)*SP + s)*VL + d] = make_float2(v0, v1);
    }
}

__device__ __forceinline__ float sigm(float x) {
    return 1.f / (1.f + __expf(-x));
}

// ---------------------------------------------------------------------------
// Fused GEMM + CSS gating + scatter.
// C[8192,3072] = A[8192,1024] @ g_Wall, 128x128x16 double-buffered,
// 256 threads, 8x8 micro-tile split 4+4 (rows {ty*4, 64+ty*4}, cols
// {tx*4, 64+tx*4}) for conflict-free LDS.128.
// ---------------------------------------------------------------------------
#define BM 128
#define BN 128
#define BK 16
#define KTILES (DIM/BK)   // 64

__global__ __launch_bounds__(256) void gemm_css_kernel(const float* __restrict__ A) {
    __shared__ float As[2][BK][BM];       // [k][m]
    __shared__ float Bs[2][BK][BN+4];

    const int tid = threadIdx.x;
    const int bm = blockIdx.y * BM;
    const int bn = blockIdx.x * BN;

    // A load: r = tid&127 (row), cbase = (tid>>7)*8 (k offset), 2 float4
    const int ar_ = tid & 127;
    const int ac_ = (tid >> 7) * 8;
    const float* Aptr = A + (size_t)(bm + ar_) * DIM + ac_;
    // B load: kr = tid>>4 (k row), tx4 = (tid&15)*4, cols {tx4, 64+tx4}
    const int bkr = tid >> 4;
    const int btx4 = (tid & 15) * 4;
    const float* Bptr = g_Wall + (size_t)bkr * NTOT + bn + btx4;

    const int ty = tid >> 4, tx = tid & 15;

    float4 a0, a1, b0, b1;
    a0 = *(const float4*)(Aptr + 0);
    a1 = *(const float4*)(Aptr + 4);
    b0 = *(const float4*)(Bptr);
    b1 = *(const float4*)(Bptr + 64);

    As[0][ac_+0][ar_] = a0.x; As[0][ac_+1][ar_] = a0.y;
    As[0][ac_+2][ar_] = a0.z; As[0][ac_+3][ar_] = a0.w;
    As[0][ac_+4][ar_] = a1.x; As[0][ac_+5][ar_] = a1.y;
    As[0][ac_+6][ar_] = a1.z; As[0][ac_+7][ar_] = a1.w;
    *(float4*)&Bs[0][bkr][btx4]      = b0;
    *(float4*)&Bs[0][bkr][64 + btx4] = b1;
    __syncthreads();

    float acc[8][8];
    #pragma unroll
    for (int i = 0; i < 8; i++)
        #pragma unroll
        for (int j = 0; j < 8; j++) acc[i][j] = 0.f;

    int buf = 0;
    for (int t = 0; t < KTILES; t++) {
        if (t < KTILES - 1) {
            const float* Ap = Aptr + (t + 1) * BK;
            a0 = *(const float4*)(Ap + 0);
            a1 = *(const float4*)(Ap + 4);
            const float* Bp = Bptr + (size_t)(t + 1) * BK * NTOT;
            b0 = *(const float4*)(Bp);
            b1 = *(const float4*)(Bp + 64);
        }
        #pragma unroll
        for (int kk = 0; kk < BK; kk++) {
            float ar[8], br[8];
            *(float4*)&ar[0] = *(float4*)&As[buf][kk][ty*4];
            *(float4*)&ar[4] = *(float4*)&As[buf][kk][64 + ty*4];
            *(float4*)&br[0] = *(float4*)&Bs[buf][kk][tx*4];
            *(float4*)&br[4] = *(float4*)&Bs[buf][kk][64 + tx*4];
            #pragma unroll
            for (int i = 0; i < 8; i++)
                #pragma unroll
                for (int j = 0; j < 8; j++)
                    acc[i][j] += ar[i] * br[j];
        }
        if (t < KTILES - 1) {
            int nb = buf ^ 1;
            As[nb][ac_+0][ar_] = a0.x; As[nb][ac_+1][ar_] = a0.y;
            As[nb][ac_+2][ar_] = a0.z; As[nb][ac_+3][ar_] = a0.w;
            As[nb][ac_+4][ar_] = a1.x; As[nb][ac_+5][ar_] = a1.y;
            As[nb][ac_+6][ar_] = a1.z; As[nb][ac_+7][ar_] = a1.w;
            *(float4*)&Bs[nb][bkr][btx4]      = b0;
            *(float4*)&Bs[nb][bkr][64 + btx4] = b1;
            __syncthreads();
            buf = nb;
        }
    }

    // Epilogue: CSS gate + scatter. cols(j): j<4 -> bn+tx*4+j ; j>=4 -> bn+64+tx*4+j-4
    float bias[8];
    #pragma unroll
    for (int j = 0; j < 8; j++) {
        int cj = bn + ((j < 4) ? (tx*4 + j) : (64 + tx*4 + (j - 4)));
        bias[j] = g_ball[cj];
    }
    #pragma unroll
    for (int i = 0; i < 8; i++) {
        int r = bm + ((i < 4) ? (ty*4 + i) : (64 + ty*4 + (i - 4)));
        int b = r >> 11;        // / 2048
        int s = r & 2047;
        #pragma unroll
        for (int g = 0; g < 2; g++) {
            float v0 = (acc[i][g*4+0] + bias[g*4+0]) * sigm(acc[i][g*4+1] + bias[g*4+1]);
            float v1 = (acc[i][g*4+2] + bias[g*4+2]) * sigm(acc[i][g*4+3] + bias[g*4+3]);
            int P = (bn + g*64 + tx*4) >> 1;   // even
            scatter2(P, b, s, v0, v1);
        }
    }
}

// ---------------------------------------------------------------------------
// Fill padded key rows (s in [2048,2064)) with bias-only constants for k, v.
// ---------------------------------------------------------------------------
__global__ void pad_fill() {
    int idx = blockIdx.x * blockDim.x + threadIdx.x;
    const int total = BATCH * 16 * 1280;   // value-cols [256,1536)
    if (idx >= total) return;
    int c = 256 + (idx % 1280);
    int t = idx / 1280;
    int sp = 2048 + (t & 15);
    int b = t >> 4;
    float val = g_ball[2*c] * sigm(g_ball[2*c + 1]);
    if (c < 512) {
        int l = c - 256; int h = l >> 4, d = l & 15;
        g_k[((size_t)((b*NH + h)*QL + d))*SP + sp] = val;
    } else {
        int l = c - 512; int h = l >> 6, d = l & 63;
        g_v[((size_t)(b*NH + h)*SP + sp)*VL + d] = val;
    }
}

// ---------------------------------------------------------------------------
// Flash attention. Grid (16 q-tiles of 128, 16 heads, 4 batch), 128 threads.
// Thread (qg=tid>>3, cg=tid&7): 8 q-rows {qg*8..}, 8 v-cols {cg*4, 32+cg*4}.
// 32-key tiles; thread computes scores for keys {cg, cg+8, cg+16, cg+24}.
// ---------------------------------------------------------------------------
__global__ __launch_bounds__(128) void attn_kernel(float* __restrict__ out) {
    const int qt = blockIdx.x, h = blockIdx.y, b = blockIdx.z;
    const int bh = b * NH + h;

    __shared__ float q_s[QL][128];
    __shared__ float k_s[QL][32];
    __shared__ float v_s[32][VL];
    __shared__ float p_s[32][132];

    const int tid = threadIdx.x;
    const int qg = tid >> 3, cg = tid & 7;

    // load q tile (d-major, contiguous)
    {
        int d = tid >> 3, c0 = (tid & 7) * 16;
        const float* src = g_q + ((size_t)(bh*QL + d))*SP + qt*128 + c0;
        #pragma unroll
        for (int u = 0; u < 4; u++)
            *(float4*)&q_s[d][c0 + u*4] = *(const float4*)(src + u*4);
    }

    float O[8][8];
    float m_run[8], l_run[8];
    #pragma unroll
    for (int i = 0; i < 8; i++) {
        m_run[i] = -1e30f; l_run[i] = 0.f;
        #pragma unroll
        for (int j = 0; j < 8; j++) O[i][j] = 0.f;
    }

    const float* kbase = g_k + (size_t)bh * QL * SP;
    const float* vbase = g_v + (size_t)bh * SP * VL;

    const int NKT = (SP + 31) / 32;   // 65
    for (int kt = 0; kt < NKT; kt++) {
        const int k0 = kt * 32;
        __syncthreads();
        // k tile [d][32]
        {
            int d = tid >> 3, c0 = (tid & 7) * 4;
            float4 kv = (k0 + c0 + 3 < SP)
                ? *(const float4*)(kbase + (size_t)d*SP + k0 + c0)
                : make_float4(0.f, 0.f, 0.f, 0.f);
            *(float4*)&k_s[d][c0] = kv;
        }
        // v tile [32][64]
        {
            int r = tid >> 2, c0 = (tid & 3) * 16;
            const float* vp = vbase + (size_t)(k0 + r)*VL + c0;
            bool ok = (k0 + r) < SP;
            #pragma unroll
            for (int u = 0; u < 4; u++)
                *(float4*)&v_s[r][c0 + u*4] = ok ? *(const float4*)(vp + u*4)
                                                 : make_float4(0.f, 0.f, 0.f, 0.f);
        }
        __syncthreads();

        // scores: s[m][i] for keys cg+8m, rows qg*8+i
        float s[4][8];
        #pragma unroll
        for (int m = 0; m < 4; m++)
            #pragma unroll
            for (int i = 0; i < 8; i++) s[m][i] = 0.f;
        #pragma unroll
        for (int d = 0; d < QL; d++) {
            float a[8];
            *(float4*)&a[0] = *(float4*)&q_s[d][qg*8];
            *(float4*)&a[4] = *(float4*)&q_s[d][qg*8 + 4];
            #pragma unroll
            for (int m = 0; m < 4; m++) {
                float kv = k_s[d][cg + 8*m];
                #pragma unroll
                for (int i = 0; i < 8; i++) s[m][i] += a[i] * kv;
            }
        }
        #pragma unroll
        for (int m = 0; m < 4; m++) {
            bool valid = (k0 + cg + 8*m) < SP;
            #pragma unroll
            for (int i = 0; i < 8; i++)
                s[m][i] = valid ? s[m][i] * 0.125f : -1e30f;
        }
        // per-row max across the 32 keys of this tile
        float mt[8];
        #pragma unroll
        for (int i = 0; i < 8; i++) {
            float v = fmaxf(fmaxf(s[0][i], s[1][i]), fmaxf(s[2][i], s[3][i]));
            v = fmaxf(v, __shfl_xor_sync(0xffffffffu, v, 1));
            v = fmaxf(v, __shfl_xor_sync(0xffffffffu, v, 2));
            v = fmaxf(v, __shfl_xor_sync(0xffffffffu, v, 4));
            mt[i] = v;
        }
        #pragma unroll
        for (int i = 0; i < 8; i++) {
            float mn = fmaxf(m_run[i], mt[i]);
            float alpha = __expf(m_run[i] - mn);
            m_run[i] = mn;
            l_run[i] *= alpha;
            #pragma unroll
            for (int j = 0; j < 8; j++) O[i][j] *= alpha;
        }
        float ls[8];
        #pragma unroll
        for (int i = 0; i < 8; i++) ls[i] = 0.f;
        #pragma unroll
        for (int m = 0; m < 4; m++)
            #pragma unroll
            for (int i = 0; i < 8; i++) {
                float p = __expf(s[m][i] - m_run[i]);
                s[m][i] = p;
                ls[i] += p;
            }
        #pragma unroll
        for (int i = 0; i < 8; i++) {
            float v = ls[i];
            v += __shfl_xor_sync(0xffffffffu, v, 1);
            v += __shfl_xor_sync(0xffffffffu, v, 2);
            v += __shfl_xor_sync(0xffffffffu, v, 4);
            l_run[i] += v;
        }
        // probs to smem (warp-local exchange)
        #pragma unroll
        for (int m = 0; m < 4; m++) {
            *(float4*)&p_s[cg + 8*m][qg*8]     = make_float4(s[m][0], s[m][1], s[m][2], s[m][3]);
            *(float4*)&p_s[cg + 8*m][qg*8 + 4] = make_float4(s[m][4], s[m][5], s[m][6], s[m][7]);
        }
        __syncwarp();

        // PV over all 32 keys
        #pragma unroll 4
        for (int key = 0; key < 32; key++) {
            float pr[8], vr[8];
            *(float4*)&pr[0] = *(float4*)&p_s[key][qg*8];
            *(float4*)&pr[4] = *(float4*)&p_s[key][qg*8 + 4];
            *(float4*)&vr[0] = *(float4*)&v_s[key][cg*4];
            *(float4*)&vr[4] = *(float4*)&v_s[key][32 + cg*4];
            #pragma unroll
            for (int i = 0; i < 8; i++)
                #pragma unroll
                for (int j = 0; j < 8; j++)
                    O[i][j] += pr[i] * vr[j];
        }
    }

    // write output: cols {h*64 + cg*4, h*64 + 32 + cg*4}
    #pragma unroll
    for (int i = 0; i < 8; i++) {
        float inv = 1.f / l_run[i];
        int qrow = qt*128 + qg*8 + i;
        float* op = out + ((size_t)(b*SEQ + qrow))*(NH*VL) + h*VL;
        *(float4*)&op[cg*4]      = make_float4(O[i][0]*inv, O[i][1]*inv, O[i][2]*inv, O[i][3]*inv);
        *(float4*)&op[32 + cg*4] = make_float4(O[i][4]*inv, O[i][5]*inv, O[i][6]*inv, O[i][7]*inv);
    }
}

// ---------------------------------------------------------------------------
extern "C" void kernel_launch(void* const* d_in, const int* in_sizes, int n_in,
                              void* d_out, int out_size) {
    const float* x   = (const float*)d_in[0];
    const float* Wq  = (const float*)d_in[1];
    const float* bq  = (const float*)d_in[2];
    const float* Wqc = (const float*)d_in[3];
    const float* bqc = (const float*)d_in[4];
    const float* Wk  = (const float*)d_in[5];
    const float* bk  = (const float*)d_in[6];
    const float* Wkc = (const float*)d_in[7];
    const float* bkc = (const float*)d_in[8];
    const float* Wv  = (const float*)d_in[9];
    const float* bv  = (const float*)d_in[10];
    const float* Wvc = (const float*)d_in[11];
    const float* bvc = (const float*)d_in[12];
    float* out = (float*)d_out;

    pack_weights<<<(DIM*NTOT + 255)/256, 256>>>(Wq,bq,Wqc,bqc,Wk,bk,Wkc,bkc,Wv,bv,Wvc,bvc);

    pad_fill<<<(BATCH*16*1280 + 255)/256, 256>>>();

    dim3 gg(NTOT / BN, MROWS / BM);
    gemm_css_kernel<<<gg, 256>>>(x);

    dim3 ga(SEQ / 128, NH, BATCH);
    attn_kernel<<<ga, 128>>>(out);
}

// round 5
// speedup vs baseline: 4.2284x; 2.2327x over previous
#include <cuda_runtime.h>
#include <cuda_bf16.h>
#include <cstdint>
#include <math.h>

// Problem constants
#define BATCH 4
#define SEQ   2048
#define SP    2064            // padded sequence (pad = 16)
#define DIM   1024
#define NH    16
#define QL    16
#define VL    64
#define NTOT  3072            // interleaved: col 2p = value, col 2p+1 = gate
#define MROWS (BATCH*SEQ)     // 8192

// -------- device scratch --------
__device__ float g_Wt[(size_t)NTOT * DIM];      // transposed tf32 weights [n][k]
__device__ float g_x32[(size_t)MROWS * DIM];    // tf32-converted x
__device__ float g_ball[NTOT];
__device__ float g_q[(size_t)BATCH * NH * SP * QL];   // [bh][s][d]
__device__ float g_k[(size_t)BATCH * NH * SP * QL];   // [bh][s][d]
__device__ float g_v[(size_t)BATCH * NH * SP * VL];   // [bh][s][d]

__device__ __forceinline__ float to_tf32(float x) {
    uint32_t u;
    asm("cvt.rna.tf32.f32 %0, %1;" : "=r"(u) : "f"(x));
    return __uint_as_float(u);
}
__device__ __forceinline__ float sigm(float x) { return 1.f / (1.f + __expf(-x)); }

__device__ __forceinline__ void mma16n8k8(float* d, const float* a, const float* b) {
    asm volatile("mma.sync.aligned.m16n8k8.row.col.f32.tf32.tf32.f32 "
        "{%0,%1,%2,%3}, {%4,%5,%6,%7}, {%8,%9}, {%0,%1,%2,%3};"
        : "+f"(d[0]), "+f"(d[1]), "+f"(d[2]), "+f"(d[3])
        : "r"(__float_as_uint(a[0])), "r"(__float_as_uint(a[1])),
          "r"(__float_as_uint(a[2])), "r"(__float_as_uint(a[3])),
          "r"(__float_as_uint(b[0])), "r"(__float_as_uint(b[1])));
}

// ======================= prep kernels =======================
__global__ void fill_bias(const float* __restrict__ bq,  const float* __restrict__ bqc,
                          const float* __restrict__ bk,  const float* __restrict__ bkc,
                          const float* __restrict__ bv,  const float* __restrict__ bvc) {
    int idx = blockIdx.x * blockDim.x + threadIdx.x;
    if (idx >= NTOT) return;
    int p = idx >> 1;
    bool gate = (idx & 1);
    float bb;
    if (p < 256)      bb = gate ? bqc[p]      : bq[p];
    else if (p < 512) bb = gate ? bkc[p-256]  : bk[p-256];
    else              bb = gate ? bvc[p-512]  : bv[p-512];
    g_ball[idx] = bb;
}

__device__ __forceinline__ float fetch_w(int k, int n,
        const float* Wq, const float* Wqc, const float* Wk, const float* Wkc,
        const float* Wv, const float* Wvc) {
    int p = n >> 1;
    bool gate = (n & 1);
    if (p < 256)      return gate ? Wqc[k*256 + p]        : Wq[k*256 + p];
    if (p < 512)      { int l = p-256; return gate ? Wkc[k*256 + l]  : Wk[k*256 + l]; }
    { int l = p-512; return gate ? Wvc[k*1024 + l] : Wv[k*1024 + l]; }
}

// transpose W into g_Wt[n][k] (tf32-converted). grid (96, 32), 256 threads
__global__ void transpose_w(const float* __restrict__ Wq,  const float* __restrict__ Wqc,
                            const float* __restrict__ Wk,  const float* __restrict__ Wkc,
                            const float* __restrict__ Wv,  const float* __restrict__ Wvc) {
    __shared__ float tile[32][33];
    int n0 = blockIdx.x * 32, k0 = blockIdx.y * 32;
    int tx = threadIdx.x & 31, ty = threadIdx.x >> 5;
    #pragma unroll
    for (int r = ty; r < 32; r += 8)
        tile[tx][r] = fetch_w(k0 + r, n0 + tx, Wq, Wqc, Wk, Wkc, Wv, Wvc);
    __syncthreads();
    #pragma unroll
    for (int r = ty; r < 32; r += 8)
        g_Wt[(size_t)(n0 + r) * DIM + k0 + tx] = to_tf32(tile[r][tx]);
}

// convert x to tf32
__global__ void xcvt(const float* __restrict__ x) {
    size_t i = ((size_t)blockIdx.x * blockDim.x + threadIdx.x) * 4;
    float4 v = *(const float4*)(x + i);
    v.x = to_tf32(v.x); v.y = to_tf32(v.y); v.z = to_tf32(v.z); v.w = to_tf32(v.w);
    *(float4*)(((float*)g_x32) + i) = v;
}

// padded key rows (s in [2048,2064)) bias-only constants for k, v
__global__ void pad_fill() {
    int idx = blockIdx.x * blockDim.x + threadIdx.x;
    const int total = BATCH * 16 * 1280;
    if (idx >= total) return;
    int c = 256 + (idx % 1280);
    int t = idx / 1280;
    int sp = 2048 + (t & 15);
    int b = t >> 4;
    float val = g_ball[2*c] * sigm(g_ball[2*c + 1]);
    if (c < 512) {
        int l = c - 256; int h = l >> 4, d = l & 15;
        g_k[((size_t)(b*NH + h) * SP + sp) * QL + d] = val;
    } else {
        int l = c - 512; int h = l >> 6, d = l & 63;
        g_v[((size_t)(b*NH + h) * SP + sp) * VL + d] = val;
    }
}

// ======================= mma.sync tf32 GEMM + CSS epilogue =======================
// C[8192,3072] = g_x32 @ g_Wt^T. 128x128x16 double-buffered, 256 threads,
// 8 warps in 2(m)x4(n), warp tile 64x32 as 4x4 m16n8k8 mma tiles.
// Smem rows padded to stride 20 floats -> conflict-free fragment LDS.
#define KT 64            // 1024/16 stages
#define SSTR 20          // smem row stride (floats)

__global__ __launch_bounds__(256) void gemm_mma() {
    __shared__ float As[2][128 * SSTR];
    __shared__ float Bs[2][128 * SSTR];

    const int tid  = threadIdx.x;
    const int wid  = tid >> 5, lane = tid & 31;
    const int wm   = wid & 1,  wn   = wid >> 1;
    const int lg   = lane >> 2, lq  = lane & 3;
    const int bm   = blockIdx.y * 128;
    const int bn   = blockIdx.x * 128;

    // loader: f = i*256 + tid -> row = f>>2, kq = (f&3)*4  (2 float4 each, rows 0..63 / 64..127)
    const int lrow = tid >> 2;
    const int lkq  = (tid & 3) * 4;
    const float* Aptr = g_x32 + (size_t)(bm + lrow) * DIM + lkq;
    const float* Bptr = g_Wt  + (size_t)(bn + lrow) * DIM + lkq;
    const uint32_t soff0 = lrow * SSTR + lkq;
    const uint32_t soff1 = (lrow + 64) * SSTR + lkq;

    float4 pa0, pa1, pb0, pb1;

    // stage 0
    pa0 = *(const float4*)(Aptr);
    pa1 = *(const float4*)(Aptr + (size_t)64 * DIM);
    pb0 = *(const float4*)(Bptr);
    pb1 = *(const float4*)(Bptr + (size_t)64 * DIM);
    *(float4*)&As[0][soff0] = pa0;
    *(float4*)&As[0][soff1] = pa1;
    *(float4*)&Bs[0][soff0] = pb0;
    *(float4*)&Bs[0][soff1] = pb1;
    __syncthreads();

    float acc[4][4][4];
    #pragma unroll
    for (int i = 0; i < 4; i++)
        #pragma unroll
        for (int j = 0; j < 4; j++)
            #pragma unroll
            for (int r = 0; r < 4; r++) acc[i][j][r] = 0.f;

    int buf = 0;
    for (int t = 0; t < KT; t++) {
        if (t < KT - 1) {
            const float* Ap = Aptr + (t + 1) * 16;
            const float* Bp = Bptr + (t + 1) * 16;
            pa0 = *(const float4*)(Ap);
            pa1 = *(const float4*)(Ap + (size_t)64 * DIM);
            pb0 = *(const float4*)(Bp);
            pb1 = *(const float4*)(Bp + (size_t)64 * DIM);
        }
        const float* Ab = As[buf];
        const float* Bb = Bs[buf];
        #pragma unroll
        for (int ks = 0; ks < 2; ks++) {
            const int kk = ks * 8;
            float a[4][4], b[4][2];
            #pragma unroll
            for (int mt = 0; mt < 4; mt++) {
                int r0 = wm*64 + mt*16 + lg;
                a[mt][0] = Ab[r0*SSTR + kk + lq];
                a[mt][1] = Ab[(r0+8)*SSTR + kk + lq];
                a[mt][2] = Ab[r0*SSTR + kk + lq + 4];
                a[mt][3] = Ab[(r0+8)*SSTR + kk + lq + 4];
            }
            #pragma unroll
            for (int nt = 0; nt < 4; nt++) {
                int n0 = wn*32 + nt*8 + lg;
                b[nt][0] = Bb[n0*SSTR + kk + lq];
                b[nt][1] = Bb[n0*SSTR + kk + lq + 4];
            }
            #pragma unroll
            for (int mt = 0; mt < 4; mt++)
                #pragma unroll
                for (int nt = 0; nt < 4; nt++)
                    mma16n8k8(acc[mt][nt], a[mt], b[nt]);
        }
        if (t < KT - 1) {
            int nb = buf ^ 1;
            __syncthreads();
            *(float4*)&As[nb][soff0] = pa0;
            *(float4*)&As[nb][soff1] = pa1;
            *(float4*)&Bs[nb][soff0] = pb0;
            *(float4*)&Bs[nb][soff1] = pb1;
            __syncthreads();
            buf = nb;
        }
    }

    // ---- epilogue: CSS gate + scatter (c0,c1)=(value,gate) per thread ----
    #pragma unroll
    for (int mt = 0; mt < 4; mt++) {
        int mrow0 = bm + wm*64 + mt*16 + lg;
        #pragma unroll
        for (int nt = 0; nt < 4; nt++) {
            int jc = bn + wn*32 + nt*8 + 2*lq;   // packed col of c0 (even)
            float bv = g_ball[jc];
            float bg = g_ball[jc + 1];
            int p = jc >> 1;                      // output feature index
            #pragma unroll
            for (int half = 0; half < 2; half++) {
                int m = mrow0 + 8*half;
                float val = (acc[mt][nt][2*half] + bv) * sigm(acc[mt][nt][2*half + 1] + bg);
                int b_ = m >> 11;
                int s  = m & 2047;
                if (p < 256) {
                    g_q[((size_t)(b_*NH + (p >> 4)) * SP + s) * QL + (p & 15)] = val;
                } else if (p < 512) {
                    int l = p - 256;
                    g_k[((size_t)(b_*NH + (l >> 4)) * SP + s) * QL + (l & 15)] = val;
                } else {
                    int l = p - 512;
                    g_v[((size_t)(b_*NH + (l >> 6)) * SP + s) * VL + (l & 63)] = val;
                }
            }
        }
    }
}

// ======================= flash attention (fp32) =======================
__global__ __launch_bounds__(128) void attn_kernel(float* __restrict__ out) {
    const int qt = blockIdx.x, h = blockIdx.y, b = blockIdx.z;
    const int bh = b * NH + h;

    __shared__ float q_s[QL][128];
    __shared__ float k_s[QL][33];
    __shared__ float v_s[32][VL];
    __shared__ float p_s[32][132];

    const int tid = threadIdx.x;
    const int qg = tid >> 3, cg = tid & 7;

    // load q tile (s-major -> transposed to [d][row])
    {
        int r = tid;
        const float* src = g_q + ((size_t)bh * SP + qt*128 + r) * QL;
        float qv[QL];
        #pragma unroll
        for (int u = 0; u < 4; u++) {
            float4 t4 = *(const float4*)(src + u*4);
            qv[u*4+0] = t4.x; qv[u*4+1] = t4.y; qv[u*4+2] = t4.z; qv[u*4+3] = t4.w;
        }
        #pragma unroll
        for (int d = 0; d < QL; d++) q_s[d][r] = qv[d];
    }

    float O[8][8];
    float m_run[8], l_run[8];
    #pragma unroll
    for (int i = 0; i < 8; i++) {
        m_run[i] = -1e30f; l_run[i] = 0.f;
        #pragma unroll
        for (int j = 0; j < 8; j++) O[i][j] = 0.f;
    }

    const float* kbase = g_k + (size_t)bh * SP * QL;
    const float* vbase = g_v + (size_t)bh * SP * VL;

    const int NKT = (SP + 31) / 32;   // 65
    for (int kt = 0; kt < NKT; kt++) {
        const int k0 = kt * 32;
        __syncthreads();
        // k tile: [32 keys][16 d] -> transposed k_s[d][key]
        {
            int key = tid >> 2, dq = (tid & 3) * 4;
            int gk = k0 + key;
            float4 kv = (gk < SP) ? *(const float4*)(kbase + (size_t)gk * QL + dq)
                                  : make_float4(0.f, 0.f, 0.f, 0.f);
            k_s[dq+0][key] = kv.x; k_s[dq+1][key] = kv.y;
            k_s[dq+2][key] = kv.z; k_s[dq+3][key] = kv.w;
        }
        // v tile [32][64]
        {
            int r = tid >> 2, c0 = (tid & 3) * 16;
            const float* vp = vbase + (size_t)(k0 + r) * VL + c0;
            bool ok = (k0 + r) < SP;
            #pragma unroll
            for (int u = 0; u < 4; u++)
                *(float4*)&v_s[r][c0 + u*4] = ok ? *(const float4*)(vp + u*4)
                                                 : make_float4(0.f, 0.f, 0.f, 0.f);
        }
        __syncthreads();

        // scores
        float s[4][8];
        #pragma unroll
        for (int m = 0; m < 4; m++)
            #pragma unroll
            for (int i = 0; i < 8; i++) s[m][i] = 0.f;
        #pragma unroll
        for (int d = 0; d < QL; d++) {
            float a[8];
            *(float4*)&a[0] = *(float4*)&q_s[d][qg*8];
            *(float4*)&a[4] = *(float4*)&q_s[d][qg*8 + 4];
            #pragma unroll
            for (int m = 0; m < 4; m++) {
                float kv = k_s[d][cg + 8*m];
                #pragma unroll
                for (int i = 0; i < 8; i++) s[m][i] += a[i] * kv;
            }
        }
        #pragma unroll
        for (int m = 0; m < 4; m++) {
            bool valid = (k0 + cg + 8*m) < SP;
            #pragma unroll
            for (int i = 0; i < 8; i++)
                s[m][i] = valid ? s[m][i] * 0.125f : -1e30f;
        }
        float mt[8];
        #pragma unroll
        for (int i = 0; i < 8; i++) {
            float v = fmaxf(fmaxf(s[0][i], s[1][i]), fmaxf(s[2][i], s[3][i]));
            v = fmaxf(v, __shfl_xor_sync(0xffffffffu, v, 1));
            v = fmaxf(v, __shfl_xor_sync(0xffffffffu, v, 2));
            v = fmaxf(v, __shfl_xor_sync(0xffffffffu, v, 4));
            mt[i] = v;
        }
        #pragma unroll
        for (int i = 0; i < 8; i++) {
            float mn = fmaxf(m_run[i], mt[i]);
            float alpha = __expf(m_run[i] - mn);
            m_run[i] = mn;
            l_run[i] *= alpha;
            #pragma unroll
            for (int j = 0; j < 8; j++) O[i][j] *= alpha;
        }
        float ls[8];
        #pragma unroll
        for (int i = 0; i < 8; i++) ls[i] = 0.f;
        #pragma unroll
        for (int m = 0; m < 4; m++)
            #pragma unroll
            for (int i = 0; i < 8; i++) {
                float p = __expf(s[m][i] - m_run[i]);
                s[m][i] = p;
                ls[i] += p;
            }
        #pragma unroll
        for (int i = 0; i < 8; i++) {
            float v = ls[i];
            v += __shfl_xor_sync(0xffffffffu, v, 1);
            v += __shfl_xor_sync(0xffffffffu, v, 2);
            v += __shfl_xor_sync(0xffffffffu, v, 4);
            l_run[i] += v;
        }
        #pragma unroll
        for (int m = 0; m < 4; m++) {
            *(float4*)&p_s[cg + 8*m][qg*8]     = make_float4(s[m][0], s[m][1], s[m][2], s[m][3]);
            *(float4*)&p_s[cg + 8*m][qg*8 + 4] = make_float4(s[m][4], s[m][5], s[m][6], s[m][7]);
        }
        __syncwarp();

        #pragma unroll 4
        for (int key = 0; key < 32; key++) {
            float pr[8], vr[8];
            *(float4*)&pr[0] = *(float4*)&p_s[key][qg*8];
            *(float4*)&pr[4] = *(float4*)&p_s[key][qg*8 + 4];
            *(float4*)&vr[0] = *(float4*)&v_s[key][cg*4];
            *(float4*)&vr[4] = *(float4*)&v_s[key][32 + cg*4];
            #pragma unroll
            for (int i = 0; i < 8; i++)
                #pragma unroll
                for (int j = 0; j < 8; j++)
                    O[i][j] += pr[i] * vr[j];
        }
    }

    #pragma unroll
    for (int i = 0; i < 8; i++) {
        float inv = 1.f / l_run[i];
        int qrow = qt*128 + qg*8 + i;
        float* op = out + ((size_t)(b*SEQ + qrow)) * (NH*VL) + h*VL;
        *(float4*)&op[cg*4]      = make_float4(O[i][0]*inv, O[i][1]*inv, O[i][2]*inv, O[i][3]*inv);
        *(float4*)&op[32 + cg*4] = make_float4(O[i][4]*inv, O[i][5]*inv, O[i][6]*inv, O[i][7]*inv);
    }
}

// ---------------------------------------------------------------------------
extern "C" void kernel_launch(void* const* d_in, const int* in_sizes, int n_in,
                              void* d_out, int out_size) {
    const float* x   = (const float*)d_in[0];
    const float* Wq  = (const float*)d_in[1];
    const float* bq  = (const float*)d_in[2];
    const float* Wqc = (const float*)d_in[3];
    const float* bqc = (const float*)d_in[4];
    const float* Wk  = (const float*)d_in[5];
    const float* bk  = (const float*)d_in[6];
    const float* Wkc = (const float*)d_in[7];
    const float* bkc = (const float*)d_in[8];
    const float* Wv  = (const float*)d_in[9];
    const float* bv  = (const float*)d_in[10];
    const float* Wvc = (const float*)d_in[11];
    const float* bvc = (const float*)d_in[12];
    float* out = (float*)d_out;

    fill_bias<<<(NTOT + 255)/256, 256>>>(bq, bqc, bk, bkc, bv, bvc);
    transpose_w<<<dim3(NTOT/32, DIM/32), 256>>>(Wq, Wqc, Wk, Wkc, Wv, Wvc);
    xcvt<<<(MROWS*DIM/4 + 255)/256, 256>>>(x);
    pad_fill<<<(BATCH*16*1280 + 255)/256, 256>>>();

    gemm_mma<<<dim3(NTOT/128, MROWS/128), 256>>>();

    attn_kernel<<<dim3(SEQ/128, NH, BATCH), 128>>>(out);
}

// round 7
// speedup vs baseline: 7.0618x; 1.6701x over previous
#include <cuda_runtime.h>
#include <cuda_bf16.h>
#include <cstdint>
#include <math.h>

// Problem constants
#define BATCH 4
#define SEQ   2048
#define SP    2064            // padded sequence (pad = 16)
#define DIM   1024
#define NH    16
#define QL    16
#define VL    64
#define NTOT  3072            // interleaved: col 2p = value, col 2p+1 = gate
#define MROWS (BATCH*SEQ)     // 8192

// -------- device scratch --------
__device__ float g_Wt[(size_t)NTOT * DIM];      // transposed tf32 weights [n][k]
__device__ float g_x32[(size_t)MROWS * DIM];    // tf32-converted x
__device__ float g_ball[NTOT];
__device__ float g_q[(size_t)BATCH * NH * SP * QL];   // [bh][s][d]
__device__ float g_k[(size_t)BATCH * NH * SP * QL];   // [bh][s][d]
__device__ float g_vt[(size_t)BATCH * NH * VL * SP];  // [bh][d][s]  (transposed!)

__device__ __forceinline__ float to_tf32(float x) {
    uint32_t u;
    asm("cvt.rna.tf32.f32 %0, %1;" : "=r"(u) : "f"(x));
    return __uint_as_float(u);
}
__device__ __forceinline__ float sigm(float x) { return 1.f / (1.f + __expf(-x)); }

__device__ __forceinline__ void mma16n8k8(float* d, const float* a, const float* b) {
    asm volatile("mma.sync.aligned.m16n8k8.row.col.f32.tf32.tf32.f32 "
        "{%0,%1,%2,%3}, {%4,%5,%6,%7}, {%8,%9}, {%0,%1,%2,%3};"
        : "+f"(d[0]), "+f"(d[1]), "+f"(d[2]), "+f"(d[3])
        : "r"(__float_as_uint(a[0])), "r"(__float_as_uint(a[1])),
          "r"(__float_as_uint(a[2])), "r"(__float_as_uint(a[3])),
          "r"(__float_as_uint(b[0])), "r"(__float_as_uint(b[1])));
}

// ======================= prep kernels =======================
__global__ void fill_bias(const float* __restrict__ bq,  const float* __restrict__ bqc,
                          const float* __restrict__ bk,  const float* __restrict__ bkc,
                          const float* __restrict__ bv,  const float* __restrict__ bvc) {
    int idx = blockIdx.x * blockDim.x + threadIdx.x;
    if (idx >= NTOT) return;
    int p = idx >> 1;
    bool gate = (idx & 1);
    float bb;
    if (p < 256)      bb = gate ? bqc[p]      : bq[p];
    else if (p < 512) bb = gate ? bkc[p-256]  : bk[p-256];
    else              bb = gate ? bvc[p-512]  : bv[p-512];
    g_ball[idx] = bb;
}

// padded key rows (s in [2048,2064)) bias-only constants for k, v(transposed)
__global__ void pad_fill() {
    int idx = blockIdx.x * blockDim.x + threadIdx.x;
    const int total = BATCH * 16 * 1280;
    if (idx >= total) return;
    int c = 256 + (idx % 1280);
    int t = idx / 1280;
    int sp = 2048 + (t & 15);
    int b = t >> 4;
    float val = g_ball[2*c] * sigm(g_ball[2*c + 1]);
    if (c < 512) {
        int l = c - 256; int h = l >> 4, d = l & 15;
        g_k[((size_t)(b*NH + h) * SP + sp) * QL + d] = val;
    } else {
        int l = c - 512; int h = l >> 6, d = l & 63;
        g_vt[((size_t)(b*NH + h) * VL + d) * SP + sp] = val;
    }
}

__device__ __forceinline__ float fetch_w(int k, int n,
        const float* Wq, const float* Wqc, const float* Wk, const float* Wkc,
        const float* Wv, const float* Wvc) {
    int p = n >> 1;
    bool gate = (n & 1);
    if (p < 256)      return gate ? Wqc[k*256 + p]        : Wq[k*256 + p];
    if (p < 512)      { int l = p-256; return gate ? Wkc[k*256 + l]  : Wk[k*256 + l]; }
    { int l = p-512; return gate ? Wvc[k*1024 + l] : Wv[k*1024 + l]; }
}

// transpose W into g_Wt[n][k] (tf32-converted)
__global__ void transpose_w(const float* __restrict__ Wq,  const float* __restrict__ Wqc,
                            const float* __restrict__ Wk,  const float* __restrict__ Wkc,
                            const float* __restrict__ Wv,  const float* __restrict__ Wvc) {
    __shared__ float tile[32][33];
    int n0 = blockIdx.x * 32, k0 = blockIdx.y * 32;
    int tx = threadIdx.x & 31, ty = threadIdx.x >> 5;
    #pragma unroll
    for (int r = ty; r < 32; r += 8)
        tile[tx][r] = fetch_w(k0 + r, n0 + tx, Wq, Wqc, Wk, Wkc, Wv, Wvc);
    __syncthreads();
    #pragma unroll
    for (int r = ty; r < 32; r += 8)
        g_Wt[(size_t)(n0 + r) * DIM + k0 + tx] = to_tf32(tile[r][tx]);
}

// convert x to tf32
__global__ void xcvt(const float* __restrict__ x) {
    size_t i = ((size_t)blockIdx.x * blockDim.x + threadIdx.x) * 4;
    float4 v = *(const float4*)(x + i);
    v.x = to_tf32(v.x); v.y = to_tf32(v.y); v.z = to_tf32(v.z); v.w = to_tf32(v.w);
    *(float4*)(((float*)g_x32) + i) = v;
}

// ======================= mma.sync tf32 GEMM + CSS epilogue =======================
#define KT 64            // 1024/16 stages
#define SSTR 20          // smem row stride (floats)

__global__ __launch_bounds__(256) void gemm_mma() {
    __shared__ float As[2][128 * SSTR];
    __shared__ float Bs[2][128 * SSTR];

    const int tid  = threadIdx.x;
    const int wid  = tid >> 5, lane = tid & 31;
    const int wm   = wid & 1,  wn   = wid >> 1;
    const int lg   = lane >> 2, lq  = lane & 3;
    const int bm   = blockIdx.y * 128;
    const int bn   = blockIdx.x * 128;

    const int lrow = tid >> 2;
    const int lkq  = (tid & 3) * 4;
    const float* Aptr = g_x32 + (size_t)(bm + lrow) * DIM + lkq;
    const float* Bptr = g_Wt  + (size_t)(bn + lrow) * DIM + lkq;
    const uint32_t soff0 = lrow * SSTR + lkq;
    const uint32_t soff1 = (lrow + 64) * SSTR + lkq;

    float4 pa0, pa1, pb0, pb1;

    pa0 = *(const float4*)(Aptr);
    pa1 = *(const float4*)(Aptr + (size_t)64 * DIM);
    pb0 = *(const float4*)(Bptr);
    pb1 = *(const float4*)(Bptr + (size_t)64 * DIM);
    *(float4*)&As[0][soff0] = pa0;
    *(float4*)&As[0][soff1] = pa1;
    *(float4*)&Bs[0][soff0] = pb0;
    *(float4*)&Bs[0][soff1] = pb1;
    __syncthreads();

    float acc[4][4][4];
    #pragma unroll
    for (int i = 0; i < 4; i++)
        #pragma unroll
        for (int j = 0; j < 4; j++)
            #pragma unroll
            for (int r = 0; r < 4; r++) acc[i][j][r] = 0.f;

    int buf = 0;
    for (int t = 0; t < KT; t++) {
        if (t < KT - 1) {
            const float* Ap = Aptr + (t + 1) * 16;
            const float* Bp = Bptr + (t + 1) * 16;
            pa0 = *(const float4*)(Ap);
            pa1 = *(const float4*)(Ap + (size_t)64 * DIM);
            pb0 = *(const float4*)(Bp);
            pb1 = *(const float4*)(Bp + (size_t)64 * DIM);
        }
        const float* Ab = As[buf];
        const float* Bb = Bs[buf];
        #pragma unroll
        for (int ks = 0; ks < 2; ks++) {
            const int kk = ks * 8;
            float a[4][4], b[4][2];
            #pragma unroll
            for (int mt = 0; mt < 4; mt++) {
                int r0 = wm*64 + mt*16 + lg;
                a[mt][0] = Ab[r0*SSTR + kk + lq];
                a[mt][1] = Ab[(r0+8)*SSTR + kk + lq];
                a[mt][2] = Ab[r0*SSTR + kk + lq + 4];
                a[mt][3] = Ab[(r0+8)*SSTR + kk + lq + 4];
            }
            #pragma unroll
            for (int nt = 0; nt < 4; nt++) {
                int n0 = wn*32 + nt*8 + lg;
                b[nt][0] = Bb[n0*SSTR + kk + lq];
                b[nt][1] = Bb[n0*SSTR + kk + lq + 4];
            }
            #pragma unroll
            for (int mt = 0; mt < 4; mt++)
                #pragma unroll
                for (int nt = 0; nt < 4; nt++)
                    mma16n8k8(acc[mt][nt], a[mt], b[nt]);
        }
        if (t < KT - 1) {
            int nb = buf ^ 1;
            __syncthreads();
            *(float4*)&As[nb][soff0] = pa0;
            *(float4*)&As[nb][soff1] = pa1;
            *(float4*)&Bs[nb][soff0] = pb0;
            *(float4*)&Bs[nb][soff1] = pb1;
            __syncthreads();
            buf = nb;
        }
    }

    // ---- epilogue: CSS gate + scatter (c0,c1)=(value,gate) per thread ----
    #pragma unroll
    for (int mt = 0; mt < 4; mt++) {
        int mrow0 = bm + wm*64 + mt*16 + lg;
        #pragma unroll
        for (int nt = 0; nt < 4; nt++) {
            int jc = bn + wn*32 + nt*8 + 2*lq;   // packed col of c0 (even)
            float bv = g_ball[jc];
            float bg = g_ball[jc + 1];
            int p = jc >> 1;
            #pragma unroll
            for (int half = 0; half < 2; half++) {
                int m = mrow0 + 8*half;
                float val = (acc[mt][nt][2*half] + bv) * sigm(acc[mt][nt][2*half + 1] + bg);
                int b_ = m >> 11;
                int s  = m & 2047;
                if (p < 256) {
                    g_q[((size_t)(b_*NH + (p >> 4)) * SP + s) * QL + (p & 15)] = val;
                } else if (p < 512) {
                    int l = p - 256;
                    g_k[((size_t)(b_*NH + (l >> 4)) * SP + s) * QL + (l & 15)] = val;
                } else {
                    int l = p - 512;
                    g_vt[((size_t)(b_*NH + (l >> 6)) * VL + (l & 63)) * SP + s] = val;
                }
            }
        }
    }
}

// ======================= tensor-core flash attention =======================
// CTA: 128 q-rows, 4 warps (one 32-row strip each). 32-key tiles.
// QK: A=Q frags (preloaded, scale folded), B = k_s [key][d].
// Softmax on C fragments. P -> per-warp smem. PV: A=P, B = v_s [vcol][key]
// (V stored transposed in gmem as [bh][d][s]).
#define PSTR 36

__global__ __launch_bounds__(128) void attn_mma(float* __restrict__ out) {
    const int qt = blockIdx.x, h = blockIdx.y, b = blockIdx.z;
    const int bh = b * NH + h;

    __shared__ float q_s[128 * 20];
    __shared__ float k_s[32 * 20];
    __shared__ float v_s[64 * PSTR];
    __shared__ float p_s[4][32 * PSTR];

    const int tid = threadIdx.x;
    const int wid = tid >> 5, lane = tid & 31;
    const int lg = lane >> 2, lq = lane & 3;

    // stage Q tile [128][16] -> q_s stride 20
    {
        const float* src = g_q + ((size_t)bh * SP + qt*128 + tid) * QL;
        #pragma unroll
        for (int u = 0; u < 4; u++)
            *(float4*)&q_s[tid*20 + u*4] = *(const float4*)(src + u*4);
    }
    __syncthreads();

    // Q fragments (softmax scale 0.125 folded in)
    float qa[2][2][4];
    #pragma unroll
    for (int mt = 0; mt < 2; mt++)
        #pragma unroll
        for (int kk = 0; kk < 2; kk++) {
            int r0 = wid*32 + mt*16 + lg;
            qa[mt][kk][0] = q_s[r0*20 + kk*8 + lq]           * 0.125f;
            qa[mt][kk][1] = q_s[(r0+8)*20 + kk*8 + lq]       * 0.125f;
            qa[mt][kk][2] = q_s[r0*20 + kk*8 + lq + 4]       * 0.125f;
            qa[mt][kk][3] = q_s[(r0+8)*20 + kk*8 + lq + 4]   * 0.125f;
        }

    float O[2][8][4];
    #pragma unroll
    for (int mt = 0; mt < 2; mt++)
        #pragma unroll
        for (int nt = 0; nt < 8; nt++)
            #pragma unroll
            for (int c = 0; c < 4; c++) O[mt][nt][c] = 0.f;
    float m_run[4], l_run[4];
    #pragma unroll
    for (int r = 0; r < 4; r++) { m_run[r] = -1e30f; l_run[r] = 0.f; }

    const float* kb = g_k  + (size_t)bh * SP * QL;
    const float* vb = g_vt + (size_t)bh * VL * SP;
    float* pw = p_s[wid];

    const int NKT = (SP + 31) / 32;   // 65
    for (int kt = 0; kt < NKT; kt++) {
        const int k0 = kt * 32;
        __syncthreads();
        // k tile [32 keys][16 d], stride 20
        {
            int r = tid >> 2, c = (tid & 3) * 4;
            float4 kv = (k0 + r < SP) ? *(const float4*)(kb + (size_t)(k0 + r)*QL + c)
                                      : make_float4(0.f,0.f,0.f,0.f);
            *(float4*)&k_s[r*20 + c] = kv;
        }
        // v tile [64 vcols][32 keys], stride 36 (gmem already [d][s])
        {
            int d = tid >> 1, c0 = (tid & 1) * 16;
            const float* vp = vb + (size_t)d * SP + k0;
            #pragma unroll
            for (int u = 0; u < 4; u++) {
                int cc = c0 + u*4;
                *(float4*)&v_s[d*PSTR + cc] = (k0 + cc < SP)
                    ? *(const float4*)(vp + cc) : make_float4(0.f,0.f,0.f,0.f);
            }
        }
        __syncthreads();

        // ---- QK ----
        float sc[2][4][4];
        #pragma unroll
        for (int mt = 0; mt < 2; mt++)
            #pragma unroll
            for (int nt = 0; nt < 4; nt++)
                #pragma unroll
                for (int c = 0; c < 4; c++) sc[mt][nt][c] = 0.f;
        #pragma unroll
        for (int kk = 0; kk < 2; kk++) {
            #pragma unroll
            for (int nt = 0; nt < 4; nt++) {
                float bb[2];
                bb[0] = k_s[(nt*8 + lg)*20 + kk*8 + lq];
                bb[1] = k_s[(nt*8 + lg)*20 + kk*8 + lq + 4];
                #pragma unroll
                for (int mt = 0; mt < 2; mt++)
                    mma16n8k8(sc[mt][nt], qa[mt][kk], bb);
            }
        }
        // mask (only last partial tile)
        if (k0 + 32 > SP) {
            #pragma unroll
            for (int nt = 0; nt < 4; nt++)
                #pragma unroll
                for (int c = 0; c < 4; c++) {
                    int col = k0 + nt*8 + 2*lq + (c & 1);
                    if (col >= SP) { sc[0][nt][c] = -1e30f; sc[1][nt][c] = -1e30f; }
                }
        }

        // ---- softmax ----
        float mloc[4];
        #pragma unroll
        for (int mt = 0; mt < 2; mt++) {
            float v0 = fmaxf(fmaxf(sc[mt][0][0], sc[mt][0][1]), fmaxf(sc[mt][1][0], sc[mt][1][1]));
            v0 = fmaxf(v0, fmaxf(fmaxf(sc[mt][2][0], sc[mt][2][1]), fmaxf(sc[mt][3][0], sc[mt][3][1])));
            float v1 = fmaxf(fmaxf(sc[mt][0][2], sc[mt][0][3]), fmaxf(sc[mt][1][2], sc[mt][1][3]));
            v1 = fmaxf(v1, fmaxf(fmaxf(sc[mt][2][2], sc[mt][2][3]), fmaxf(sc[mt][3][2], sc[mt][3][3])));
            mloc[2*mt]   = v0;
            mloc[2*mt+1] = v1;
        }
        #pragma unroll
        for (int r = 0; r < 4; r++) {
            float v = mloc[r];
            v = fmaxf(v, __shfl_xor_sync(0xffffffffu, v, 1));
            v = fmaxf(v, __shfl_xor_sync(0xffffffffu, v, 2));
            mloc[r] = v;
        }
        float alpha[4];
        #pragma unroll
        for (int r = 0; r < 4; r++) {
            float mn = fmaxf(m_run[r], mloc[r]);
            alpha[r] = __expf(m_run[r] - mn);
            m_run[r] = mn;
            l_run[r] *= alpha[r];
        }
        float lsum[4] = {0.f, 0.f, 0.f, 0.f};
        #pragma unroll
        for (int mt = 0; mt < 2; mt++)
            #pragma unroll
            for (int nt = 0; nt < 4; nt++) {
                float p0 = __expf(sc[mt][nt][0] - m_run[2*mt]);
                float p1 = __expf(sc[mt][nt][1] - m_run[2*mt]);
                float p2 = __expf(sc[mt][nt][2] - m_run[2*mt+1]);
                float p3 = __expf(sc[mt][nt][3] - m_run[2*mt+1]);
                lsum[2*mt]   += p0 + p1;
                lsum[2*mt+1] += p2 + p3;
                *(float2*)&pw[(mt*16 + lg)*PSTR     + nt*8 + 2*lq] = make_float2(p0, p1);
                *(float2*)&pw[(mt*16 + lg + 8)*PSTR + nt*8 + 2*lq] = make_float2(p2, p3);
            }
        #pragma unroll
        for (int r = 0; r < 4; r++) {
            float v = lsum[r];
            v += __shfl_xor_sync(0xffffffffu, v, 1);
            v += __shfl_xor_sync(0xffffffffu, v, 2);
            l_run[r] += v;
        }
        // rescale O
        #pragma unroll
        for (int mt = 0; mt < 2; mt++)
            #pragma unroll
            for (int nt = 0; nt < 8; nt++) {
                O[mt][nt][0] *= alpha[2*mt];
                O[mt][nt][1] *= alpha[2*mt];
                O[mt][nt][2] *= alpha[2*mt+1];
                O[mt][nt][3] *= alpha[2*mt+1];
            }
        __syncwarp();

        // ---- PV ----
        #pragma unroll
        for (int kk = 0; kk < 4; kk++) {
            float pa[2][4];
            #pragma unroll
            for (int mt = 0; mt < 2; mt++) {
                int r0 = mt*16 + lg;
                pa[mt][0] = pw[r0*PSTR + kk*8 + lq];
                pa[mt][1] = pw[(r0+8)*PSTR + kk*8 + lq];
                pa[mt][2] = pw[r0*PSTR + kk*8 + lq + 4];
                pa[mt][3] = pw[(r0+8)*PSTR + kk*8 + lq + 4];
            }
            #pragma unroll
            for (int nt = 0; nt < 8; nt++) {
                float bb[2];
                bb[0] = v_s[(nt*8 + lg)*PSTR + kk*8 + lq];
                bb[1] = v_s[(nt*8 + lg)*PSTR + kk*8 + lq + 4];
                #pragma unroll
                for (int mt = 0; mt < 2; mt++)
                    mma16n8k8(O[mt][nt], pa[mt], bb);
            }
        }
    }

    // ---- write output ----
    #pragma unroll
    for (int mt = 0; mt < 2; mt++)
        #pragma unroll
        for (int half = 0; half < 2; half++) {
            int row = qt*128 + wid*32 + mt*16 + lg + half*8;
            float inv = 1.f / l_run[2*mt + half];
            float* op = out + ((size_t)(b*SEQ + row)) * (NH*VL) + h*VL;
            #pragma unroll
            for (int nt = 0; nt < 8; nt++)
                *(float2*)&op[nt*8 + 2*lq] = make_float2(O[mt][nt][2*half]*inv,
                                                         O[mt][nt][2*half+1]*inv);
        }
}

// ---------------------------------------------------------------------------
extern "C" void kernel_launch(void* const* d_in, const int* in_sizes, int n_in,
                              void* d_out, int out_size) {
    const float* x   = (const float*)d_in[0];
    const float* Wq  = (const float*)d_in[1];
    const float* bq  = (const float*)d_in[2];
    const float* Wqc = (const float*)d_in[3];
    const float* bqc = (const float*)d_in[4];
    const float* Wk  = (const float*)d_in[5];
    const float* bk  = (const float*)d_in[6];
    const float* Wkc = (const float*)d_in[7];
    const float* bkc = (const float*)d_in[8];
    const float* Wv  = (const float*)d_in[9];
    const float* bv  = (const float*)d_in[10];
    const float* Wvc = (const float*)d_in[11];
    const float* bvc = (const float*)d_in[12];
    float* out = (float*)d_out;

    fill_bias<<<(NTOT + 255)/256, 256>>>(bq, bqc, bk, bkc, bv, bvc);
    pad_fill<<<(BATCH*16*1280 + 255)/256, 256>>>();
    transpose_w<<<dim3(NTOT/32, DIM/32), 256>>>(Wq, Wqc, Wk, Wkc, Wv, Wvc);
    xcvt<<<(MROWS*DIM/4 + 255)/256, 256>>>(x);

    gemm_mma<<<dim3(NTOT/128, MROWS/128), 256>>>();

    attn_mma<<<dim3(SEQ/128, NH, BATCH), 128>>>(out);
}

// round 9
// speedup vs baseline: 7.1690x; 1.0152x over previous
#include <cuda_runtime.h>
#include <cuda_bf16.h>
#include <cstdint>
#include <math.h>

// Problem constants
#define BATCH 4
#define SEQ   2048
#define SP    2064            // padded sequence (pad = 16)
#define DIM   1024
#define NH    16
#define QL    16
#define VL    64
#define NTOT  3072            // interleaved: col 2p = value, col 2p+1 = gate
#define MROWS (BATCH*SEQ)     // 8192

// -------- device scratch --------
__device__ float g_Wt[(size_t)NTOT * DIM];      // transposed tf32 weights [n][k]
__device__ float g_ball[NTOT];
__device__ float g_q[(size_t)BATCH * NH * SP * QL];   // [bh][s][d]  (raw fp32)
__device__ float g_k[(size_t)BATCH * NH * SP * QL];   // [bh][s][d]  (raw fp32)
__device__ float g_vt[(size_t)BATCH * NH * VL * SP];  // [bh][d][s]  (tf32-rounded)

__device__ __forceinline__ float to_tf32(float x) {
    uint32_t u;
    asm("cvt.rna.tf32.f32 %0, %1;" : "=r"(u) : "f"(x));
    return __uint_as_float(u);
}
__device__ __forceinline__ float4 tf4(float4 v) {
    v.x = to_tf32(v.x); v.y = to_tf32(v.y); v.z = to_tf32(v.z); v.w = to_tf32(v.w);
    return v;
}
__device__ __forceinline__ float sigm(float x) { return 1.f / (1.f + __expf(-x)); }

__device__ __forceinline__ uint32_t smem_u32(const void* p) {
    uint32_t a;
    asm("{ .reg .u64 t; cvta.to.shared.u64 t, %1; cvt.u32.u64 %0, t; }" : "=r"(a) : "l"(p));
    return a;
}
__device__ __forceinline__ void cpa16(uint32_t dst, const float* src, bool ok) {
    int sz = ok ? 16 : 0;
    asm volatile("cp.async.cg.shared.global [%0], [%1], 16, %2;"
                 :: "r"(dst), "l"(src), "r"(sz));
}
#define CPA_COMMIT() asm volatile("cp.async.commit_group;" ::: "memory")

__device__ __forceinline__ void mma16n8k8(float* d, const float* a, const float* b) {
    asm volatile("mma.sync.aligned.m16n8k8.row.col.f32.tf32.tf32.f32 "
        "{%0,%1,%2,%3}, {%4,%5,%6,%7}, {%8,%9}, {%0,%1,%2,%3};"
        : "+f"(d[0]), "+f"(d[1]), "+f"(d[2]), "+f"(d[3])
        : "r"(__float_as_uint(a[0])), "r"(__float_as_uint(a[1])),
          "r"(__float_as_uint(a[2])), "r"(__float_as_uint(a[3])),
          "r"(__float_as_uint(b[0])), "r"(__float_as_uint(b[1])));
}

// ======================= prep kernels =======================
__global__ void fill_bias(const float* __restrict__ bq,  const float* __restrict__ bqc,
                          const float* __restrict__ bk,  const float* __restrict__ bkc,
                          const float* __restrict__ bv,  const float* __restrict__ bvc) {
    int idx = blockIdx.x * blockDim.x + threadIdx.x;
    if (idx >= NTOT) return;
    int p = idx >> 1;
    bool gate = (idx & 1);
    float bb;
    if (p < 256)      bb = gate ? bqc[p]      : bq[p];
    else if (p < 512) bb = gate ? bkc[p-256]  : bk[p-256];
    else              bb = gate ? bvc[p-512]  : bv[p-512];
    g_ball[idx] = bb;
}

// padded key rows (s in [2048,2064)) bias-only constants for k, v(transposed)
__global__ void pad_fill() {
    int idx = blockIdx.x * blockDim.x + threadIdx.x;
    const int total = BATCH * 16 * 1280;
    if (idx >= total) return;
    int c = 256 + (idx % 1280);
    int t = idx / 1280;
    int sp = 2048 + (t & 15);
    int b = t >> 4;
    float val = g_ball[2*c] * sigm(g_ball[2*c + 1]);
    if (c < 512) {
        int l = c - 256; int h = l >> 4, d = l & 15;
        g_k[((size_t)(b*NH + h) * SP + sp) * QL + d] = val;
    } else {
        int l = c - 512; int h = l >> 6, d = l & 63;
        g_vt[((size_t)(b*NH + h) * VL + d) * SP + sp] = to_tf32(val);
    }
}

__device__ __forceinline__ float fetch_w(int k, int n,
        const float* Wq, const float* Wqc, const float* Wk, const float* Wkc,
        const float* Wv, const float* Wvc) {
    int p = n >> 1;
    bool gate = (n & 1);
    if (p < 256)      return gate ? Wqc[k*256 + p]        : Wq[k*256 + p];
    if (p < 512)      { int l = p-256; return gate ? Wkc[k*256 + l]  : Wk[k*256 + l]; }
    { int l = p-512; return gate ? Wvc[k*1024 + l] : Wv[k*1024 + l]; }
}

// transpose W into g_Wt[n][k] (tf32-converted)
__global__ void transpose_w(const float* __restrict__ Wq,  const float* __restrict__ Wqc,
                            const float* __restrict__ Wk,  const float* __restrict__ Wkc,
                            const float* __restrict__ Wv,  const float* __restrict__ Wvc) {
    __shared__ float tile[32][33];
    int n0 = blockIdx.x * 32, k0 = blockIdx.y * 32;
    int tx = threadIdx.x & 31, ty = threadIdx.x >> 5;
    #pragma unroll
    for (int r = ty; r < 32; r += 8)
        tile[tx][r] = fetch_w(k0 + r, n0 + tx, Wq, Wqc, Wk, Wkc, Wv, Wvc);
    __syncthreads();
    #pragma unroll
    for (int r = ty; r < 32; r += 8)
        g_Wt[(size_t)(n0 + r) * DIM + k0 + tx] = to_tf32(tile[r][tx]);
}

// ======================= mma.sync tf32 GEMM + CSS epilogue =======================
#define KT 64            // 1024/16 stages
#define SSTR 20          // smem row stride (floats)

__global__ __launch_bounds__(256) void gemm_mma(const float* __restrict__ x) {
    __shared__ float As[2][128 * SSTR];
    __shared__ float Bs[2][128 * SSTR];

    const int tid  = threadIdx.x;
    const int wid  = tid >> 5, lane = tid & 31;
    const int wm   = wid & 1,  wn   = wid >> 1;
    const int lg   = lane >> 2, lq  = lane & 3;
    const int bm   = blockIdx.y * 128;
    const int bn   = blockIdx.x * 128;

    const int lrow = tid >> 2;
    const int lkq  = (tid & 3) * 4;
    const float* Aptr = x     + (size_t)(bm + lrow) * DIM + lkq;
    const float* Bptr = g_Wt  + (size_t)(bn + lrow) * DIM + lkq;
    const uint32_t soff0 = lrow * SSTR + lkq;
    const uint32_t soff1 = (lrow + 64) * SSTR + lkq;

    float4 pa0, pa1, pb0, pb1;

    pa0 = *(const float4*)(Aptr);
    pa1 = *(const float4*)(Aptr + (size_t)64 * DIM);
    pb0 = *(const float4*)(Bptr);
    pb1 = *(const float4*)(Bptr + (size_t)64 * DIM);
    *(float4*)&As[0][soff0] = tf4(pa0);
    *(float4*)&As[0][soff1] = tf4(pa1);
    *(float4*)&Bs[0][soff0] = pb0;
    *(float4*)&Bs[0][soff1] = pb1;
    __syncthreads();

    float acc[4][4][4];
    #pragma unroll
    for (int i = 0; i < 4; i++)
        #pragma unroll
        for (int j = 0; j < 4; j++)
            #pragma unroll
            for (int r = 0; r < 4; r++) acc[i][j][r] = 0.f;

    int buf = 0;
    for (int t = 0; t < KT; t++) {
        if (t < KT - 1) {
            const float* Ap = Aptr + (t + 1) * 16;
            const float* Bp = Bptr + (t + 1) * 16;
            pa0 = *(const float4*)(Ap);
            pa1 = *(const float4*)(Ap + (size_t)64 * DIM);
            pb0 = *(const float4*)(Bp);
            pb1 = *(const float4*)(Bp + (size_t)64 * DIM);
        }
        const float* Ab = As[buf];
        const float* Bb = Bs[buf];
        #pragma unroll
        for (int ks = 0; ks < 2; ks++) {
            const int kk = ks * 8;
            float a[4][4], b[4][2];
            #pragma unroll
            for (int mt = 0; mt < 4; mt++) {
                int r0 = wm*64 + mt*16 + lg;
                a[mt][0] = Ab[r0*SSTR + kk + lq];
                a[mt][1] = Ab[(r0+8)*SSTR + kk + lq];
                a[mt][2] = Ab[r0*SSTR + kk + lq + 4];
                a[mt][3] = Ab[(r0+8)*SSTR + kk + lq + 4];
            }
            #pragma unroll
            for (int nt = 0; nt < 4; nt++) {
                int n0 = wn*32 + nt*8 + lg;
                b[nt][0] = Bb[n0*SSTR + kk + lq];
                b[nt][1] = Bb[n0*SSTR + kk + lq + 4];
            }
            #pragma unroll
            for (int mt = 0; mt < 4; mt++)
                #pragma unroll
                for (int nt = 0; nt < 4; nt++)
                    mma16n8k8(acc[mt][nt], a[mt], b[nt]);
        }
        if (t < KT - 1) {
            int nb = buf ^ 1;
            __syncthreads();
            *(float4*)&As[nb][soff0] = tf4(pa0);
            *(float4*)&As[nb][soff1] = tf4(pa1);
            *(float4*)&Bs[nb][soff0] = pb0;
            *(float4*)&Bs[nb][soff1] = pb1;
            __syncthreads();
            buf = nb;
        }
    }

    // ---- epilogue: CSS gate + scatter (c0,c1)=(value,gate) per thread ----
    #pragma unroll
    for (int mt = 0; mt < 4; mt++) {
        int mrow0 = bm + wm*64 + mt*16 + lg;
        #pragma unroll
        for (int nt = 0; nt < 4; nt++) {
            int jc = bn + wn*32 + nt*8 + 2*lq;   // packed col of c0 (even)
            float bv = g_ball[jc];
            float bg = g_ball[jc + 1];
            int p = jc >> 1;
            #pragma unroll
            for (int half = 0; half < 2; half++) {
                int m = mrow0 + 8*half;
                float val = (acc[mt][nt][2*half] + bv) * sigm(acc[mt][nt][2*half + 1] + bg);
                int b_ = m >> 11;
                int s  = m & 2047;
                if (p < 256) {
                    g_q[((size_t)(b_*NH + (p >> 4)) * SP + s) * QL + (p & 15)] = val;
                } else if (p < 512) {
                    int l = p - 256;
                    g_k[((size_t)(b_*NH + (l >> 4)) * SP + s) * QL + (l & 15)] = val;
                } else {
                    int l = p - 512;
                    g_vt[((size_t)(b_*NH + (l >> 6)) * VL + (l & 63)) * SP + s] = to_tf32(val);
                }
            }
        }
    }
}

// ======================= tensor-core flash attention =======================
// CTA: 128 q-rows, 4 warps. 32-key tiles, 3-stage cp.async pipeline.
// QK: 3-mma hi/lo compensation (~fp32 scores). PV: tf32 (V pre-rounded, P rna).
#define PSTR 36
#define KSTR 20
// dynamic smem layout (float offsets)
#define SM_Q   0                    // 128*20 = 2560
#define SM_K   2560                 // 3 bufs * 640
#define SM_V   4480                 // 3 bufs * 2304
#define SM_P   11392                // 4 warps * 1152
#define SM_TOT 16000                // floats (64000 bytes)

__global__ __launch_bounds__(128) void attn_mma(float* __restrict__ out) {
    extern __shared__ float sm[];
    const int qt = blockIdx.x, h = blockIdx.y, b = blockIdx.z;
    const int bh = b * NH + h;

    const int tid = threadIdx.x;
    const int wid = tid >> 5, lane = tid & 31;
    const int lg = lane >> 2, lq = lane & 3;

    const float* kb = g_k  + (size_t)bh * SP * QL;
    const float* vb = g_vt + (size_t)bh * VL * SP;

    const uint32_t smbase = smem_u32(sm);

    // cp.async issue for one 32-key tile into buffer bufi
    const int krow = tid >> 2, kfq = (tid & 3) * 4;
    const int NKT = (SP + 31) / 32;   // 65

    // ---- stage Q tile [128][16] ----
    {
        const float* src = g_q + ((size_t)bh * SP + qt*128 + tid) * QL;
        #pragma unroll
        for (int u = 0; u < 4; u++)
            *(float4*)&sm[SM_Q + tid*KSTR + u*4] = *(const float4*)(src + u*4);
    }

    // prologue: issue tiles 0,1
    #pragma unroll
    for (int pt = 0; pt < 2; pt++) {
        const int k0 = pt * 32;
        const int kbuf = SM_K + pt * 640, vbuf = SM_V + pt * 2304;
        {
            int gk = k0 + krow;
            bool ok = gk < SP;
            cpa16(smbase + (kbuf + krow*KSTR + kfq) * 4, kb + (size_t)(ok ? gk : 0) * QL + kfq, ok);
        }
        #pragma unroll
        for (int it = 0; it < 4; it++) {
            int chunk = it * 128 + tid;
            int d = chunk >> 3, cp = (chunk & 7) * 4;
            bool ok = (k0 + cp + 4) <= SP;
            cpa16(smbase + (vbuf + d*PSTR + cp) * 4, vb + (size_t)d * SP + (ok ? k0 + cp : 0), ok);
        }
        CPA_COMMIT();
    }
    __syncthreads();

    // Q fragments hi/lo (softmax scale 0.125 folded in before split)
    float qh[2][2][4], ql[2][2][4];
    #pragma unroll
    for (int mt = 0; mt < 2; mt++)
        #pragma unroll
        for (int kk = 0; kk < 2; kk++) {
            int r0 = wid*32 + mt*16 + lg;
            #pragma unroll
            for (int e = 0; e < 4; e++) {
                int rr = r0 + ((e & 1) ? 8 : 0);
                int cc = kk*8 + lq + ((e >= 2) ? 4 : 0);
                float qs = sm[SM_Q + rr*KSTR + cc] * 0.125f;
                float hh = to_tf32(qs);
                qh[mt][kk][e] = hh;
                ql[mt][kk][e] = to_tf32(qs - hh);
            }
        }

    float O[2][8][4];
    #pragma unroll
    for (int mt = 0; mt < 2; mt++)
        #pragma unroll
        for (int nt = 0; nt < 8; nt++)
            #pragma unroll
            for (int c = 0; c < 4; c++) O[mt][nt][c] = 0.f;
    float m_run[4], l_run[4];
    #pragma unroll
    for (int r = 0; r < 4; r++) { m_run[r] = -1e30f; l_run[r] = 0.f; }

    float* pw = sm + SM_P + wid * 1152;

    for (int kt = 0; kt < NKT; kt++) {
        const int k0 = kt * 32;
        // wait for tile kt (pending groups: kt, kt+1 at most)
        if (kt + 1 < NKT) asm volatile("cp.async.wait_group 1;" ::: "memory");
        else              asm volatile("cp.async.wait_group 0;" ::: "memory");
        __syncthreads();
        // issue tile kt+2 into buffer (kt+2)%3
        if (kt + 2 < NKT) {
            const int k2 = (kt + 2) * 32;
            const int bi = (kt + 2) % 3;
            const int kbuf = SM_K + bi * 640, vbuf = SM_V + bi * 2304;
            {
                int gk = k2 + krow;
                bool ok = gk < SP;
                cpa16(smbase + (kbuf + krow*KSTR + kfq) * 4, kb + (size_t)(ok ? gk : 0) * QL + kfq, ok);
            }
            #pragma unroll
            for (int it = 0; it < 4; it++) {
                int chunk = it * 128 + tid;
                int d = chunk >> 3, cp = (chunk & 7) * 4;
                bool ok = (k2 + cp + 4) <= SP;
                cpa16(smbase + (vbuf + d*PSTR + cp) * 4, vb + (size_t)d * SP + (ok ? k2 + cp : 0), ok);
            }
            CPA_COMMIT();
        }

        const float* kbuf = sm + SM_K + (kt % 3) * 640;
        const float* vbuf = sm + SM_V + (kt % 3) * 2304;

        // ---- QK (3-mma compensated) ----
        float sc[2][4][4];
        #pragma unroll
        for (int mt = 0; mt < 2; mt++)
            #pragma unroll
            for (int nt = 0; nt < 4; nt++)
                #pragma unroll
                for (int c = 0; c < 4; c++) sc[mt][nt][c] = 0.f;
        #pragma unroll
        for (int kk = 0; kk < 2; kk++) {
            #pragma unroll
            for (int nt = 0; nt < 4; nt++) {
                float r0 = kbuf[(nt*8 + lg)*KSTR + kk*8 + lq];
                float r1 = kbuf[(nt*8 + lg)*KSTR + kk*8 + lq + 4];
                float h0 = to_tf32(r0), h1 = to_tf32(r1);
                float bh_[2] = { h0, h1 };
                float bl_[2] = { to_tf32(r0 - h0), to_tf32(r1 - h1) };
                #pragma unroll
                for (int mt = 0; mt < 2; mt++) {
                    mma16n8k8(sc[mt][nt], qh[mt][kk], bh_);
                    mma16n8k8(sc[mt][nt], ql[mt][kk], bh_);
                    mma16n8k8(sc[mt][nt], qh[mt][kk], bl_);
                }
            }
        }
        // mask (only last partial tile)
        if (k0 + 32 > SP) {
            #pragma unroll
            for (int nt = 0; nt < 4; nt++)
                #pragma unroll
                for (int c = 0; c < 4; c++) {
                    int col = k0 + nt*8 + 2*lq + (c & 1);
                    if (col >= SP) { sc[0][nt][c] = -1e30f; sc[1][nt][c] = -1e30f; }
                }
        }

        // ---- softmax ----
        float mloc[4];
        #pragma unroll
        for (int mt = 0; mt < 2; mt++) {
            float v0 = fmaxf(fmaxf(sc[mt][0][0], sc[mt][0][1]), fmaxf(sc[mt][1][0], sc[mt][1][1]));
            v0 = fmaxf(v0, fmaxf(fmaxf(sc[mt][2][0], sc[mt][2][1]), fmaxf(sc[mt][3][0], sc[mt][3][1])));
            float v1 = fmaxf(fmaxf(sc[mt][0][2], sc[mt][0][3]), fmaxf(sc[mt][1][2], sc[mt][1][3]));
            v1 = fmaxf(v1, fmaxf(fmaxf(sc[mt][2][2], sc[mt][2][3]), fmaxf(sc[mt][3][2], sc[mt][3][3])));
            mloc[2*mt]   = v0;
            mloc[2*mt+1] = v1;
        }
        #pragma unroll
        for (int r = 0; r < 4; r++) {
            float v = mloc[r];
            v = fmaxf(v, __shfl_xor_sync(0xffffffffu, v, 1));
            v = fmaxf(v, __shfl_xor_sync(0xffffffffu, v, 2));
            mloc[r] = v;
        }
        float alpha[4];
        #pragma unroll
        for (int r = 0; r < 4; r++) {
            float mn = fmaxf(m_run[r], mloc[r]);
            alpha[r] = __expf(m_run[r] - mn);
            m_run[r] = mn;
            l_run[r] *= alpha[r];
        }
        float lsum[4] = {0.f, 0.f, 0.f, 0.f};
        #pragma unroll
        for (int mt = 0; mt < 2; mt++)
            #pragma unroll
            for (int nt = 0; nt < 4; nt++) {
                float p0 = __expf(sc[mt][nt][0] - m_run[2*mt]);
                float p1 = __expf(sc[mt][nt][1] - m_run[2*mt]);
                float p2 = __expf(sc[mt][nt][2] - m_run[2*mt+1]);
                float p3 = __expf(sc[mt][nt][3] - m_run[2*mt+1]);
                lsum[2*mt]   += p0 + p1;
                lsum[2*mt+1] += p2 + p3;
                *(float2*)&pw[(mt*16 + lg)*PSTR     + nt*8 + 2*lq] = make_float2(to_tf32(p0), to_tf32(p1));
                *(float2*)&pw[(mt*16 + lg + 8)*PSTR + nt*8 + 2*lq] = make_float2(to_tf32(p2), to_tf32(p3));
            }
        #pragma unroll
        for (int r = 0; r < 4; r++) {
            float v = lsum[r];
            v += __shfl_xor_sync(0xffffffffu, v, 1);
            v += __shfl_xor_sync(0xffffffffu, v, 2);
            l_run[r] += v;
        }
        // rescale O
        #pragma unroll
        for (int mt = 0; mt < 2; mt++)
            #pragma unroll
            for (int nt = 0; nt < 8; nt++) {
                O[mt][nt][0] *= alpha[2*mt];
                O[mt][nt][1] *= alpha[2*mt];
                O[mt][nt][2] *= alpha[2*mt+1];
                O[mt][nt][3] *= alpha[2*mt+1];
            }
        __syncwarp();

        // ---- PV ----
        #pragma unroll
        for (int kk = 0; kk < 4; kk++) {
            float pa[2][4];
            #pragma unroll
            for (int mt = 0; mt < 2; mt++) {
                int r0 = mt*16 + lg;
                pa[mt][0] = pw[r0*PSTR + kk*8 + lq];
                pa[mt][1] = pw[(r0+8)*PSTR + kk*8 + lq];
                pa[mt][2] = pw[r0*PSTR + kk*8 + lq + 4];
                pa[mt][3] = pw[(r0+8)*PSTR + kk*8 + lq + 4];
            }
            #pragma unroll
            for (int nt = 0; nt < 8; nt++) {
                float bb[2];
                bb[0] = vbuf[(nt*8 + lg)*PSTR + kk*8 + lq];
                bb[1] = vbuf[(nt*8 + lg)*PSTR + kk*8 + lq + 4];
                #pragma unroll
                for (int mt = 0; mt < 2; mt++)
                    mma16n8k8(O[mt][nt], pa[mt], bb);
            }
        }
        __syncthreads();   // protect buffer (kt%3) before it is re-issued
    }

    // ---- write output ----
    #pragma unroll
    for (int mt = 0; mt < 2; mt++)
        #pragma unroll
        for (int half = 0; half < 2; half++) {
            int row = qt*128 + wid*32 + mt*16 + lg + half*8;
            float inv = 1.f / l_run[2*mt + half];
            float* op = out + ((size_t)(b*SEQ + row)) * (NH*VL) + h*VL;
            #pragma unroll
            for (int nt = 0; nt < 8; nt++)
                *(float2*)&op[nt*8 + 2*lq] = make_float2(O[mt][nt][2*half]*inv,
                                                         O[mt][nt][2*half+1]*inv);
        }
}

// ---------------------------------------------------------------------------
extern "C" void kernel_launch(void* const* d_in, const int* in_sizes, int n_in,
                              void* d_out, int out_size) {
    const float* x   = (const float*)d_in[0];
    const float* Wq  = (const float*)d_in[1];
    const float* bq  = (const float*)d_in[2];
    const float* Wqc = (const float*)d_in[3];
    const float* bqc = (const float*)d_in[4];
    const float* Wk  = (const float*)d_in[5];
    const float* bk  = (const float*)d_in[6];
    const float* Wkc = (const float*)d_in[7];
    const float* bkc = (const float*)d_in[8];
    const float* Wv  = (const float*)d_in[9];
    const float* bv  = (const float*)d_in[10];
    const float* Wvc = (const float*)d_in[11];
    const float* bvc = (const float*)d_in[12];
    float* out = (float*)d_out;

    static bool attr_set = false;
    if (!attr_set) {
        cudaFuncSetAttribute(attn_mma, cudaFuncAttributeMaxDynamicSharedMemorySize, SM_TOT * 4);
        attr_set = true;
    }

    fill_bias<<<(NTOT + 255)/256, 256>>>(bq, bqc, bk, bkc, bv, bvc);
    pad_fill<<<(BATCH*16*1280 + 255)/256, 256>>>();
    transpose_w<<<dim3(NTOT/32, DIM/32), 256>>>(Wq, Wqc, Wk, Wkc, Wv, Wvc);

    gemm_mma<<<dim3(NTOT/128, MROWS/128), 256>>>(x);

    attn_mma<<<dim3(SEQ/128, NH, BATCH), 128, SM_TOT * 4>>>(out);
}